// round 1
// baseline (speedup 1.0000x reference)
#include <cuda_runtime.h>
#include <cstdint>

// ---------------------------------------------------------------------------
// AFNO1D: out = softshrink-path(x) + x, fully restructured to dense GEMMs.
//   xf = x @ D1024                                   [16384 x 1024]
//   o1 = relu( xf[b]@A1[b] + xf_pi[b]@B1[b] + b1 )   blockdiag 8 x (128x128)
//   z  = sshrink( o1[b]@A2[b] + o1_pi[b]@B2[b] + b2 )
//   out= z[b] @ (D128 / 2^24) + x
// A/B matrices are built per launch from w1/w2 (cheap).
// ---------------------------------------------------------------------------

static constexpr int   CCH  = 1024;
static constexpr float C1   = 0.5f / 16777216.0f;   // 0.5 / numel
static constexpr float C2   = 1.0f / 16777216.0f;   // final idht 1/numel
static constexpr float LAMB = 0.01f;

// scratch (allocation-free rule: __device__ globals)
__device__ __align__(16) float g_D1024[1024 * 1024];
__device__ __align__(16) float g_D128 [128 * 128];
__device__ __align__(16) float g_Wsum [2 * 8 * 16384];
__device__ __align__(16) float g_T    [2 * 8 * 16384];
__device__ __align__(16) float g_U    [2 * 8 * 16384];
__device__ __align__(16) float g_V    [2 * 8 * 16384];
__device__ __align__(16) float g_Amat [2 * 8 * 16384];
__device__ __align__(16) float g_Bmat [2 * 8 * 16384];
__device__ __align__(16) float g_XF   [16384 * 1024];   // reused as z buffer later
__device__ __align__(16) float g_O1   [16384 * 1024];

// ---------------------------------------------------------------------------
// Build DHT (cas) matrices: D[k,j] = cos(2*pi*k*j/N) + sin(2*pi*k*j/N)
// ---------------------------------------------------------------------------
__global__ void k_build_D() {
    int stride = gridDim.x * blockDim.x;
    int tid = blockIdx.x * blockDim.x + threadIdx.x;
    for (int i = tid; i < 1024 * 1024; i += stride) {
        int k = i >> 10, j = i & 1023;
        int m = (k * j) & 1023;
        float s, c;
        sincospif(2.0f * (float)m * (1.0f / 1024.0f), &s, &c);
        g_D1024[i] = c + s;
    }
    for (int i = tid; i < 128 * 128; i += stride) {
        int k = i >> 7, j = i & 127;
        int m = (k * j) & 127;
        float s, c;
        sincospif(2.0f * (float)m * (1.0f / 128.0f), &s, &c);
        g_D128[i] = c + s;
    }
}

// Wsum[l][b] = w_l[0][b] + w_l[1][b]
__global__ void k_wsum(const float* __restrict__ w1, const float* __restrict__ w2) {
    int stride = gridDim.x * blockDim.x;
    int tid = blockIdx.x * blockDim.x + threadIdx.x;
    for (int i = tid; i < 2 * 131072; i += stride) {
        int l = i >> 17, rem = i & 131071;
        const float* src = l ? w2 : w1;
        g_Wsum[i] = src[rem] + src[rem + 131072];
    }
}

// ---------------------------------------------------------------------------
// Generic 128x128(xK) fp32 tile GEMM, 256 threads, 8x8 microtile, acc in regs.
// ---------------------------------------------------------------------------
__device__ __forceinline__ void mm_tile_acc(
    const float* __restrict__ Ag, int lda,
    const float* __restrict__ Bg, int ldb,
    int K, float (&acc)[8][8], float* sA, float* sB, int tid)
{
    int tx = tid & 15, ty = tid >> 4;
    for (int kk = 0; kk < K; kk += 32) {
        __syncthreads();
        // A tile: 128(m) x 32(k) -> sA[k][m] (transposed, pad 129)
        #pragma unroll
        for (int f = tid; f < 1024; f += 256) {
            int m  = f >> 3;
            int kq = (f & 7) * 4;
            float4 v = *reinterpret_cast<const float4*>(Ag + (size_t)m * lda + kk + kq);
            sA[(kq + 0) * 129 + m] = v.x;
            sA[(kq + 1) * 129 + m] = v.y;
            sA[(kq + 2) * 129 + m] = v.z;
            sA[(kq + 3) * 129 + m] = v.w;
        }
        // B tile: 32(k) x 128(n) -> sB[k][n]
        #pragma unroll
        for (int f = tid; f < 1024; f += 256) {
            int k  = f >> 5;
            int nq = (f & 31) * 4;
            *reinterpret_cast<float4*>(sB + k * 128 + nq) =
                *reinterpret_cast<const float4*>(Bg + (size_t)(kk + k) * ldb + nq);
        }
        __syncthreads();
        #pragma unroll 8
        for (int k = 0; k < 32; k++) {
            float a[8], b[8];
            #pragma unroll
            for (int i = 0; i < 8; i++) a[i] = sA[k * 129 + ty * 8 + i];
            #pragma unroll
            for (int j = 0; j < 8; j++) b[j] = sB[k * 128 + tx * 8 + j];
            #pragma unroll
            for (int i = 0; i < 8; i++)
                #pragma unroll
                for (int j = 0; j < 8; j++)
                    acc[i][j] = fmaf(a[i], b[j], acc[i][j]);
        }
    }
}

#define MM_SMEM __shared__ float sA[32 * 129]; __shared__ float sB[32 * 128]

// T[l][b] = D128 @ Wsum[l][b]   (jobs 0..15)
// U[l][b] = Wsum[l][b] @ D128   (jobs 16..31)
__global__ __launch_bounds__(256) void k_mm_TU() {
    MM_SMEM;
    int j = blockIdx.x, tid = threadIdx.x;
    const float *Ag, *Bg; float* Cg;
    if (j < 16) { Ag = g_D128;              Bg = g_Wsum + j * 16384;        Cg = g_T + j * 16384; }
    else        { Ag = g_Wsum + (j-16)*16384; Bg = g_D128;                  Cg = g_U + (j-16) * 16384; }
    float acc[8][8] = {};
    mm_tile_acc(Ag, 128, Bg, 128, 128, acc, sA, sB, tid);
    int tx = tid & 15, ty = tid >> 4;
    #pragma unroll
    for (int i = 0; i < 8; i++)
        #pragma unroll
        for (int jj = 0; jj < 8; jj++)
            Cg[(ty * 8 + i) * 128 + tx * 8 + jj] = acc[i][jj];
}

// V[l][b] = T[l][b] @ D128
__global__ __launch_bounds__(256) void k_mm_V() {
    MM_SMEM;
    int j = blockIdx.x, tid = threadIdx.x;
    float acc[8][8] = {};
    mm_tile_acc(g_T + j * 16384, 128, g_D128, 128, 128, acc, sA, sB, tid);
    int tx = tid & 15, ty = tid >> 4;
    #pragma unroll
    for (int i = 0; i < 8; i++)
        #pragma unroll
        for (int jj = 0; jj < 8; jj++)
            g_V[j * 16384 + (ty * 8 + i) * 128 + tx * 8 + jj] = acc[i][jj];
}

// A[l][b] = C1*(128*T[l][b] + V[l][sig(b)]) ; B[l][b] = C1*(128*Wsum[l][b] - U[l][sig(b)])
__global__ void k_combine() {
    int stride = gridDim.x * blockDim.x;
    int tid = blockIdx.x * blockDim.x + threadIdx.x;
    for (int i = tid; i < 2 * 131072; i += stride) {
        int l = i >> 17, rem = i & 131071;
        int b = rem >> 14, e = rem & 16383;
        int sb = (8 - b) & 7;
        int flip = l * 131072 + sb * 16384 + e;
        g_Amat[i] = C1 * (128.0f * g_T[i]    + g_V[flip]);
        g_Bmat[i] = C1 * (128.0f * g_Wsum[i] - g_U[flip]);
    }
}

// Stage 1: XF = X @ D1024.  grid = 128 mtiles * 8 ntiles
__global__ __launch_bounds__(256) void k_gemm_xf(const float* __restrict__ x) {
    MM_SMEM;
    int bx = blockIdx.x, tid = threadIdx.x;
    int mt = bx >> 3, nt = bx & 7;
    float acc[8][8] = {};
    mm_tile_acc(x + (size_t)mt * 128 * CCH, CCH, g_D1024 + nt * 128, CCH, 1024, acc, sA, sB, tid);
    int tx = tid & 15, ty = tid >> 4;
    #pragma unroll
    for (int i = 0; i < 8; i++)
        #pragma unroll
        for (int jj = 0; jj < 8; jj++)
            g_XF[(size_t)(mt * 128 + ty * 8 + i) * CCH + nt * 128 + tx * 8 + jj] = acc[i][jj];
}

__device__ __forceinline__ int partner_batch(int beta) { return (4 - beta) & 3; }

// Stage 2: O1 = relu( XF[b]@A1[b] + XFpi[b]@B1[b] + b1[0] ).  grid = 4*32*8
__global__ __launch_bounds__(256) void k_stage2(const float* __restrict__ b1) {
    MM_SMEM;
    int bx = blockIdx.x, tid = threadIdx.x;
    int b = bx & 7, nt = (bx >> 3) & 31, beta = bx >> 8;
    int rowbase  = beta * 4096 + nt * 128;
    int prowbase = partner_batch(beta) * 4096 + nt * 128;
    float acc[8][8] = {};
    mm_tile_acc(g_XF + (size_t)rowbase  * CCH + b * 128, CCH, g_Amat + b * 16384, 128, 128, acc, sA, sB, tid);
    mm_tile_acc(g_XF + (size_t)prowbase * CCH + b * 128, CCH, g_Bmat + b * 16384, 128, 128, acc, sA, sB, tid);
    int tx = tid & 15, ty = tid >> 4;
    #pragma unroll
    for (int i = 0; i < 8; i++)
        #pragma unroll
        for (int jj = 0; jj < 8; jj++) {
            int col = b * 128 + tx * 8 + jj;
            float v = acc[i][jj] + b1[col];
            g_O1[(size_t)(rowbase + ty * 8 + i) * CCH + col] = fmaxf(v, 0.0f);
        }
}

// Stage 3a: Z = softshrink( O1[b]@A2[b] + O1pi[b]@B2[b] + b2[0] ) -> reuse g_XF
__global__ __launch_bounds__(256) void k_stage3a(const float* __restrict__ b2) {
    MM_SMEM;
    int bx = blockIdx.x, tid = threadIdx.x;
    int b = bx & 7, nt = (bx >> 3) & 31, beta = bx >> 8;
    int rowbase  = beta * 4096 + nt * 128;
    int prowbase = partner_batch(beta) * 4096 + nt * 128;
    float acc[8][8] = {};
    mm_tile_acc(g_O1 + (size_t)rowbase  * CCH + b * 128, CCH, g_Amat + 131072 + b * 16384, 128, 128, acc, sA, sB, tid);
    mm_tile_acc(g_O1 + (size_t)prowbase * CCH + b * 128, CCH, g_Bmat + 131072 + b * 16384, 128, 128, acc, sA, sB, tid);
    int tx = tid & 15, ty = tid >> 4;
    #pragma unroll
    for (int i = 0; i < 8; i++)
        #pragma unroll
        for (int jj = 0; jj < 8; jj++) {
            int col = b * 128 + tx * 8 + jj;
            float v = acc[i][jj] + b2[col];
            float z = (fabsf(v) > LAMB) ? (v > 0.0f ? v - LAMB : v + LAMB) : 0.0f;
            g_XF[(size_t)(rowbase + ty * 8 + i) * CCH + col] = z;
        }
}

// Stage 3b: out = Z[b] @ D128 * C2 + x.  grid = 128 mtiles * 8 blocks
__global__ __launch_bounds__(256) void k_stage3b(const float* __restrict__ x, float* __restrict__ out) {
    MM_SMEM;
    int bx = blockIdx.x, tid = threadIdx.x;
    int mt = bx >> 3, b = bx & 7;
    float acc[8][8] = {};
    mm_tile_acc(g_XF + (size_t)mt * 128 * CCH + b * 128, CCH, g_D128, 128, 128, acc, sA, sB, tid);
    int tx = tid & 15, ty = tid >> 4;
    #pragma unroll
    for (int i = 0; i < 8; i++)
        #pragma unroll
        for (int jj = 0; jj < 8; jj++) {
            size_t idx = (size_t)(mt * 128 + ty * 8 + i) * CCH + b * 128 + tx * 8 + jj;
            out[idx] = acc[i][jj] * C2 + x[idx];
        }
}

extern "C" void kernel_launch(void* const* d_in, const int* in_sizes, int n_in,
                              void* d_out, int out_size) {
    const float* x  = (const float*)d_in[0];
    const float* w1 = (const float*)d_in[1];
    const float* b1 = (const float*)d_in[2];
    const float* w2 = (const float*)d_in[3];
    const float* b2 = (const float*)d_in[4];
    float* out = (float*)d_out;

    k_build_D<<<512, 256>>>();
    k_wsum<<<256, 256>>>(w1, w2);
    k_mm_TU<<<32, 256>>>();
    k_mm_V<<<16, 256>>>();
    k_combine<<<256, 256>>>();
    k_gemm_xf<<<1024, 256>>>(x);
    k_stage2<<<1024, 256>>>(b1);
    k_stage3a<<<1024, 256>>>(b2);
    k_stage3b<<<1024, 256>>>(x, out);
}

// round 2
// speedup vs baseline: 2.5042x; 2.5042x over previous
#include <cuda_runtime.h>
#include <cuda_bf16.h>
#include <mma.h>
#include <cstdint>

using namespace nvcuda;

// ---------------------------------------------------------------------------
// AFNO1D restructured to dense GEMMs (see round-1 derivation), now on bf16
// tensor cores (wmma/HMMA, fp32 accum). Conv path contributes ~1e-8 of the
// output (1/2^24 normalization), so bf16 is numerically free.
//   xf = x @ D1024                      [16384 x 1024]   bf16
//   o1 = relu( xf[b]@A1[b] + xf_pi[b]@B1[b] + b1 )       bf16
//   z  = sshrink( o1[b]@A2[b] + o1_pi[b]@B2[b] + b2 )    bf16
//   out= z[b] @ D128 * C2 + x                            fp32
// ---------------------------------------------------------------------------

static constexpr int   CCH  = 1024;
static constexpr float C1   = 0.5f / 16777216.0f;
static constexpr float C2   = 1.0f / 16777216.0f;
static constexpr float LAMB = 0.01f;

// fp32 precompute scratch
__device__ __align__(16) float g_D128 [128 * 128];
__device__ __align__(16) float g_Wsum [2 * 8 * 16384];
__device__ __align__(16) float g_T    [2 * 8 * 16384];
__device__ __align__(16) float g_U    [2 * 8 * 16384];
__device__ __align__(16) float g_V    [2 * 8 * 16384];

// bf16 operands
__device__ __align__(16) __nv_bfloat16 g_D1024h[1024 * 1024];
__device__ __align__(16) __nv_bfloat16 g_D128h [128 * 128];
__device__ __align__(16) __nv_bfloat16 g_Ah    [2 * 8 * 16384];
__device__ __align__(16) __nv_bfloat16 g_Bh    [2 * 8 * 16384];
__device__ __align__(16) __nv_bfloat16 g_Xh    [16384 * 1024];
__device__ __align__(16) __nv_bfloat16 g_XFh   [16384 * 1024];  // later reused for z
__device__ __align__(16) __nv_bfloat16 g_O1h   [16384 * 1024];

// ---------------------------------------------------------------------------
// Precompute kernels (fp32, tiny)
// ---------------------------------------------------------------------------
__global__ void k_build_D() {
    int stride = gridDim.x * blockDim.x;
    int tid = blockIdx.x * blockDim.x + threadIdx.x;
    for (int i = tid; i < 1024 * 1024; i += stride) {
        int k = i >> 10, j = i & 1023;
        int m = (k * j) & 1023;
        float s, c;
        sincospif(2.0f * (float)m * (1.0f / 1024.0f), &s, &c);
        g_D1024h[i] = __float2bfloat16(c + s);
    }
    for (int i = tid; i < 128 * 128; i += stride) {
        int k = i >> 7, j = i & 127;
        int m = (k * j) & 127;
        float s, c;
        sincospif(2.0f * (float)m * (1.0f / 128.0f), &s, &c);
        g_D128[i]  = c + s;
        g_D128h[i] = __float2bfloat16(c + s);
    }
}

__global__ void k_wsum(const float* __restrict__ w1, const float* __restrict__ w2) {
    int stride = gridDim.x * blockDim.x;
    int tid = blockIdx.x * blockDim.x + threadIdx.x;
    for (int i = tid; i < 2 * 131072; i += stride) {
        int l = i >> 17, rem = i & 131071;
        const float* src = l ? w2 : w1;
        g_Wsum[i] = src[rem] + src[rem + 131072];
    }
}

// fp32 128x128 tile GEMM for weight precompute
__device__ __forceinline__ void mm_tile_acc(
    const float* __restrict__ Ag, int lda,
    const float* __restrict__ Bg, int ldb,
    int K, float (&acc)[8][8], float* sA, float* sB, int tid)
{
    int tx = tid & 15, ty = tid >> 4;
    for (int kk = 0; kk < K; kk += 32) {
        __syncthreads();
        #pragma unroll
        for (int f = tid; f < 1024; f += 256) {
            int m  = f >> 3;
            int kq = (f & 7) * 4;
            float4 v = *reinterpret_cast<const float4*>(Ag + (size_t)m * lda + kk + kq);
            sA[(kq + 0) * 129 + m] = v.x;
            sA[(kq + 1) * 129 + m] = v.y;
            sA[(kq + 2) * 129 + m] = v.z;
            sA[(kq + 3) * 129 + m] = v.w;
        }
        #pragma unroll
        for (int f = tid; f < 1024; f += 256) {
            int k  = f >> 5;
            int nq = (f & 31) * 4;
            *reinterpret_cast<float4*>(sB + k * 128 + nq) =
                *reinterpret_cast<const float4*>(Bg + (size_t)(kk + k) * ldb + nq);
        }
        __syncthreads();
        #pragma unroll 8
        for (int k = 0; k < 32; k++) {
            float a[8], b[8];
            #pragma unroll
            for (int i = 0; i < 8; i++) a[i] = sA[k * 129 + ty * 8 + i];
            #pragma unroll
            for (int j = 0; j < 8; j++) b[j] = sB[k * 128 + tx * 8 + j];
            #pragma unroll
            for (int i = 0; i < 8; i++)
                #pragma unroll
                for (int j = 0; j < 8; j++)
                    acc[i][j] = fmaf(a[i], b[j], acc[i][j]);
        }
    }
}

#define MM_SMEM __shared__ float sA[32 * 129]; __shared__ float sB[32 * 128]

__global__ __launch_bounds__(256) void k_mm_TU() {
    MM_SMEM;
    int j = blockIdx.x, tid = threadIdx.x;
    const float *Ag, *Bg; float* Cg;
    if (j < 16) { Ag = g_D128;                Bg = g_Wsum + j * 16384; Cg = g_T + j * 16384; }
    else        { Ag = g_Wsum + (j-16)*16384; Bg = g_D128;             Cg = g_U + (j-16) * 16384; }
    float acc[8][8] = {};
    mm_tile_acc(Ag, 128, Bg, 128, 128, acc, sA, sB, tid);
    int tx = tid & 15, ty = tid >> 4;
    #pragma unroll
    for (int i = 0; i < 8; i++)
        #pragma unroll
        for (int jj = 0; jj < 8; jj++)
            Cg[(ty * 8 + i) * 128 + tx * 8 + jj] = acc[i][jj];
}

__global__ __launch_bounds__(256) void k_mm_V() {
    MM_SMEM;
    int j = blockIdx.x, tid = threadIdx.x;
    float acc[8][8] = {};
    mm_tile_acc(g_T + j * 16384, 128, g_D128, 128, 128, acc, sA, sB, tid);
    int tx = tid & 15, ty = tid >> 4;
    #pragma unroll
    for (int i = 0; i < 8; i++)
        #pragma unroll
        for (int jj = 0; jj < 8; jj++)
            g_V[j * 16384 + (ty * 8 + i) * 128 + tx * 8 + jj] = acc[i][jj];
}

// A[l][b] = C1*(128*T[l][b] + V[l][sig(b)]) ; B[l][b] = C1*(128*Wsum[l][b] - U[l][sig(b)])
__global__ void k_combine() {
    int stride = gridDim.x * blockDim.x;
    int tid = blockIdx.x * blockDim.x + threadIdx.x;
    for (int i = tid; i < 2 * 131072; i += stride) {
        int l = i >> 17, rem = i & 131071;
        int b = rem >> 14, e = rem & 16383;
        int sb = (8 - b) & 7;
        int flip = l * 131072 + sb * 16384 + e;
        g_Ah[i] = __float2bfloat16(C1 * (128.0f * g_T[i]    + g_V[flip]));
        g_Bh[i] = __float2bfloat16(C1 * (128.0f * g_Wsum[i] - g_U[flip]));
    }
}

__global__ void k_x2h(const float* __restrict__ x) {
    int stride = gridDim.x * blockDim.x;
    int tid = blockIdx.x * blockDim.x + threadIdx.x;
    for (int i = tid; i < 16384 * 1024 / 4; i += stride) {
        float4 v = reinterpret_cast<const float4*>(x)[i];
        __nv_bfloat162 lo = __floats2bfloat162_rn(v.x, v.y);
        __nv_bfloat162 hi = __floats2bfloat162_rn(v.z, v.w);
        reinterpret_cast<__nv_bfloat162*>(g_Xh)[i * 2]     = lo;
        reinterpret_cast<__nv_bfloat162*>(g_Xh)[i * 2 + 1] = hi;
    }
}

// ---------------------------------------------------------------------------
// bf16 wmma GEMM core: 128x128 block tile, 8 warps (4x2), warp tile 32x64.
// ---------------------------------------------------------------------------
static constexpr int SLA = 48;    // smem ld for A tile (128 x 32 bf16, padded)
static constexpr int SLB = 144;   // smem ld for B tile (32 x 128 bf16, padded)

using FragA = wmma::fragment<wmma::matrix_a, 16, 16, 16, __nv_bfloat16, wmma::row_major>;
using FragB = wmma::fragment<wmma::matrix_b, 16, 16, 16, __nv_bfloat16, wmma::row_major>;
using FragC = wmma::fragment<wmma::accumulator, 16, 16, 16, float>;

__device__ __forceinline__ void wmma_accum(
    const __nv_bfloat16* __restrict__ Ag, int lda,
    const __nv_bfloat16* __restrict__ Bg, int ldb,
    int K, FragC (&acc)[2][4],
    __nv_bfloat16* sA, __nv_bfloat16* sB, int tid)
{
    int wid = tid >> 5;
    int wr = wid & 3, wc = wid >> 2;
    for (int kk = 0; kk < K; kk += 32) {
        __syncthreads();
        #pragma unroll
        for (int f = tid; f < 512; f += 256) {      // A: 128x32
            int m = f >> 2, kq = (f & 3) * 8;
            *reinterpret_cast<uint4*>(sA + m * SLA + kq) =
                *reinterpret_cast<const uint4*>(Ag + (size_t)m * lda + kk + kq);
        }
        #pragma unroll
        for (int f = tid; f < 512; f += 256) {      // B: 32x128
            int k = f >> 4, nq = (f & 15) * 8;
            *reinterpret_cast<uint4*>(sB + k * SLB + nq) =
                *reinterpret_cast<const uint4*>(Bg + (size_t)(kk + k) * ldb + nq);
        }
        __syncthreads();
        #pragma unroll
        for (int ks = 0; ks < 32; ks += 16) {
            FragA af[2];
            FragB bf[4];
            #pragma unroll
            for (int i = 0; i < 2; i++)
                wmma::load_matrix_sync(af[i], sA + (wr * 32 + i * 16) * SLA + ks, SLA);
            #pragma unroll
            for (int j = 0; j < 4; j++)
                wmma::load_matrix_sync(bf[j], sB + ks * SLB + wc * 64 + j * 16, SLB);
            #pragma unroll
            for (int i = 0; i < 2; i++)
                #pragma unroll
                for (int j = 0; j < 4; j++)
                    wmma::mma_sync(acc[i][j], af[i], bf[j], acc[i][j]);
        }
    }
}

#define WMMA_SMEM \
    __shared__ __align__(16) __nv_bfloat16 sA[128 * SLA]; \
    __shared__ __align__(16) __nv_bfloat16 sB[32 * SLB];  \
    __shared__ __align__(16) float sE[8 * 256]

// Epilogue iteration: per accumulator fragment, stage to smem, lanes apply OP.
// OP receives (gm, gn, val) with gm,gn local to the 128x128 block tile.
#define WMMA_EPILOGUE(OP) do {                                               \
    int wid = tid >> 5, lane = tid & 31;                                     \
    int wr = wid & 3, wc = wid >> 2;                                         \
    float* sEw = sE + wid * 256;                                             \
    int er = lane >> 1, ec0 = (lane & 1) * 8;                                \
    _Pragma("unroll")                                                        \
    for (int i = 0; i < 2; i++)                                              \
        _Pragma("unroll")                                                    \
        for (int j = 0; j < 4; j++) {                                        \
            wmma::store_matrix_sync(sEw, acc[i][j], 16, wmma::mem_row_major);\
            __syncwarp();                                                    \
            int gm = wr * 32 + i * 16 + er;                                  \
            _Pragma("unroll")                                                \
            for (int c = 0; c < 8; c++) {                                    \
                int gn = wc * 64 + j * 16 + ec0 + c;                         \
                float val = sEw[er * 16 + ec0 + c];                          \
                OP;                                                          \
            }                                                                \
            __syncwarp();                                                    \
        }                                                                    \
} while (0)

// Stage 1: XFh = Xh @ D1024h.  grid = 128 mtiles * 8 ntiles
__global__ __launch_bounds__(256) void k_xf() {
    WMMA_SMEM;
    int tid = threadIdx.x, bx = blockIdx.x;
    int mt = bx >> 3, nt = bx & 7;
    FragC acc[2][4];
    #pragma unroll
    for (int i = 0; i < 2; i++)
        #pragma unroll
        for (int j = 0; j < 4; j++) wmma::fill_fragment(acc[i][j], 0.0f);
    wmma_accum(g_Xh + (size_t)mt * 128 * CCH, CCH, g_D1024h + nt * 128, CCH, 1024, acc, sA, sB, tid);
    WMMA_EPILOGUE({
        g_XFh[(size_t)(mt * 128 + gm) * CCH + nt * 128 + gn] = __float2bfloat16(val);
    });
}

__device__ __forceinline__ int partner_batch(int beta) { return (4 - beta) & 3; }

// Stage 2: O1 = relu(XF[b]@A1[b] + XFpi[b]@B1[b] + b1).  grid = 4*32*8
__global__ __launch_bounds__(256) void k_s2(const float* __restrict__ b1) {
    WMMA_SMEM;
    int tid = threadIdx.x, bx = blockIdx.x;
    int b = bx & 7, nt = (bx >> 3) & 31, beta = bx >> 8;
    int rowbase  = beta * 4096 + nt * 128;
    int prowbase = partner_batch(beta) * 4096 + nt * 128;
    FragC acc[2][4];
    #pragma unroll
    for (int i = 0; i < 2; i++)
        #pragma unroll
        for (int j = 0; j < 4; j++) wmma::fill_fragment(acc[i][j], 0.0f);
    wmma_accum(g_XFh + (size_t)rowbase  * CCH + b * 128, CCH, g_Ah + b * 16384, 128, 128, acc, sA, sB, tid);
    wmma_accum(g_XFh + (size_t)prowbase * CCH + b * 128, CCH, g_Bh + b * 16384, 128, 128, acc, sA, sB, tid);
    WMMA_EPILOGUE({
        int col = b * 128 + gn;
        float v = val + b1[col];
        g_O1h[(size_t)(rowbase + gm) * CCH + col] = __float2bfloat16(fmaxf(v, 0.0f));
    });
}

// Stage 3a: Z = sshrink(O1[b]@A2[b] + O1pi[b]@B2[b] + b2) -> reuse g_XFh
__global__ __launch_bounds__(256) void k_s3a(const float* __restrict__ b2) {
    WMMA_SMEM;
    int tid = threadIdx.x, bx = blockIdx.x;
    int b = bx & 7, nt = (bx >> 3) & 31, beta = bx >> 8;
    int rowbase  = beta * 4096 + nt * 128;
    int prowbase = partner_batch(beta) * 4096 + nt * 128;
    FragC acc[2][4];
    #pragma unroll
    for (int i = 0; i < 2; i++)
        #pragma unroll
        for (int j = 0; j < 4; j++) wmma::fill_fragment(acc[i][j], 0.0f);
    wmma_accum(g_O1h + (size_t)rowbase  * CCH + b * 128, CCH, g_Ah + 131072 + b * 16384, 128, 128, acc, sA, sB, tid);
    wmma_accum(g_O1h + (size_t)prowbase * CCH + b * 128, CCH, g_Bh + 131072 + b * 16384, 128, 128, acc, sA, sB, tid);
    WMMA_EPILOGUE({
        int col = b * 128 + gn;
        float v = val + b2[col];
        float z = (fabsf(v) > LAMB) ? (v > 0.0f ? v - LAMB : v + LAMB) : 0.0f;
        g_XFh[(size_t)(rowbase + gm) * CCH + col] = __float2bfloat16(z);
    });
}

// Stage 3b: out = Z[b] @ D128 * C2 + x.  grid = 128 mtiles * 8 blocks
__global__ __launch_bounds__(256) void k_s3b(const float* __restrict__ x, float* __restrict__ out) {
    WMMA_SMEM;
    int tid = threadIdx.x, bx = blockIdx.x;
    int mt = bx >> 3, b = bx & 7;
    FragC acc[2][4];
    #pragma unroll
    for (int i = 0; i < 2; i++)
        #pragma unroll
        for (int j = 0; j < 4; j++) wmma::fill_fragment(acc[i][j], 0.0f);
    wmma_accum(g_XFh + (size_t)mt * 128 * CCH + b * 128, CCH, g_D128h, 128, 128, acc, sA, sB, tid);
    WMMA_EPILOGUE({
        size_t idx = (size_t)(mt * 128 + gm) * CCH + b * 128 + gn;
        out[idx] = val * C2 + x[idx];
    });
}

extern "C" void kernel_launch(void* const* d_in, const int* in_sizes, int n_in,
                              void* d_out, int out_size) {
    const float* x  = (const float*)d_in[0];
    const float* w1 = (const float*)d_in[1];
    const float* b1 = (const float*)d_in[2];
    const float* w2 = (const float*)d_in[3];
    const float* b2 = (const float*)d_in[4];
    float* out = (float*)d_out;

    k_build_D<<<512, 256>>>();
    k_wsum<<<256, 256>>>(w1, w2);
    k_mm_TU<<<32, 256>>>();
    k_mm_V<<<16, 256>>>();
    k_combine<<<256, 256>>>();
    k_x2h<<<512, 256>>>(x);
    k_xf <<<1024, 256>>>();
    k_s2 <<<1024, 256>>>(b1);
    k_s3a<<<1024, 256>>>(b2);
    k_s3b<<<1024, 256>>>(x, out);
}